// round 14
// baseline (speedup 1.0000x reference)
#include <cuda_runtime.h>
#include <stdint.h>

// MXFP (E2M1-like, group=32) quantize-dequantize, bit-exact vs the JAX reference.
// Round 14: partial L2-pin experiment, 256-bit compliant. sm_103 requires
// v8.b32/v4.b64 for L2::evict_last, so the pinned half (first 67MB of input,
// fits in evict-last L2 capacity unlike R7's 134MB all-pin) is loaded with
// one ld.global.L2::evict_last.v4.b64 (8 floats/thread, width-4 group
// butterfly) while the other half + all stores stream with .cs (R2 path,
// width-8 butterfly). If L2 residency persists across graph replays,
// steady-state DRAM drops 268 -> ~200MB/iter.

__device__ __forceinline__ float mxfp_q1(float x, float inv_scale, float scale) {
    float xd = x * inv_scale;                       // exact (power-of-two scale)
    uint32_t bb = __float_as_uint(xd);
    uint32_t eb = bb & 0x7F800000u;                 // exponent field
    // mans*2 = |xd| * 2^(1-e);  m2 in [2,4) for normal xd
    float m2 = fabsf(xd) * __uint_as_float(0x7F800000u - eb);
    // RNE to integer via magic constant (matches rintf / jnp.round here)
    float r = (m2 + 12582912.0f) - 12582912.0f;
    // x_rnd = r * 2^(e-1)
    float ra = r * __uint_as_float(eb - 0x00800000u);
    ra = fminf(fmaxf(ra, 0.5f), 6.0f);              // clamp [min_repr, max_repr]
    if (fabsf(xd) <= 0.25f) ra = 0.0f;              // lim_zero flush (handles 0/denorm paths)
    uint32_t rb = (__float_as_uint(ra) & 0x7FFFFFFFu) | (bb & 0x80000000u);
    return __uint_as_float(rb) * scale;             // exact (power-of-two scale)
}

__device__ __forceinline__ float maxabs4(float4 v) {
    return fmaxf(fmaxf(fabsf(v.x), fabsf(v.y)), fmaxf(fabsf(v.z), fabsf(v.w)));
}

__device__ __forceinline__ float4 q4(float4 v, float inv_scale, float scale) {
    float4 o;
    o.x = mxfp_q1(v.x, inv_scale, scale);
    o.y = mxfp_q1(v.y, inv_scale, scale);
    o.z = mxfp_q1(v.z, inv_scale, scale);
    o.w = mxfp_q1(v.w, inv_scale, scale);
    return o;
}

// Derive per-group scale pair from group max.
__device__ __forceinline__ void make_scales(float mk, float* inv_scale, float* scale) {
    if (mk == 0.0f) mk = 1.0f;
    int e   = (int)(__float_as_uint(mk) >> 23) - 127;   // floor(log2) for normal mk
    int pot = e - 2;
    if (pot < -127) pot = -127;
    *inv_scale = __uint_as_float((uint32_t)(127 - pot) << 23);   // 2^-pot
    *scale = (pot >= -126)
           ? __uint_as_float((uint32_t)(pot + 127) << 23)        // normal 2^pot
           : __uint_as_float(0x00400000u);                       // denormal 2^-127
}

// 256-bit load with L2 evict-last (pin 32B line segment in L2).
__device__ __forceinline__ void ld_el_v4b64(const float4* p, float4* a, float4* b) {
    uint64_t r0, r1, r2, r3;
    asm volatile("ld.global.L2::evict_last.v4.b64 {%0,%1,%2,%3}, [%4];"
                 : "=l"(r0), "=l"(r1), "=l"(r2), "=l"(r3) : "l"(p));
    a->x = __uint_as_float((uint32_t)r0);  a->y = __uint_as_float((uint32_t)(r0 >> 32));
    a->z = __uint_as_float((uint32_t)r1);  a->w = __uint_as_float((uint32_t)(r1 >> 32));
    b->x = __uint_as_float((uint32_t)r2);  b->y = __uint_as_float((uint32_t)(r2 >> 32));
    b->z = __uint_as_float((uint32_t)r3);  b->w = __uint_as_float((uint32_t)(r3 >> 32));
}

__global__ __launch_bounds__(256) void mxfp_kernel(const float4* __restrict__ in,
                                                   float4* __restrict__ out,
                                                   int nq) {
    int i = blockIdx.x * blockDim.x + threadIdx.x;
    if (i >= nq) return;

    // ---- front-batched loads ----
    // Pinned half: 8 consecutive floats at float4 index 2i (region [0, 2*nq)).
    float4 a, b;
    ld_el_v4b64(in + 2 * i, &a, &b);
    // Streaming half: slabs 2,3 (R2 layout).
    float4 c = __ldcs(in + i + 2 * nq);
    float4 d = __ldcs(in + i + 3 * nq);

    // ---- group maxes ----
    // Pinned: thread owns floats [8i, 8i+8) -> group = 4 consecutive lanes.
    float mab = fmaxf(maxabs4(a), maxabs4(b));
    // Streaming: R2 layout -> group = 8 consecutive lanes.
    float mc = maxabs4(c);
    float md = maxabs4(d);

    // interleaved butterfly stages
    mab = fmaxf(mab, __shfl_xor_sync(0xFFFFFFFFu, mab, 1));
    mc  = fmaxf(mc,  __shfl_xor_sync(0xFFFFFFFFu, mc, 1));
    md  = fmaxf(md,  __shfl_xor_sync(0xFFFFFFFFu, md, 1));
    mab = fmaxf(mab, __shfl_xor_sync(0xFFFFFFFFu, mab, 2));
    mc  = fmaxf(mc,  __shfl_xor_sync(0xFFFFFFFFu, mc, 2));
    md  = fmaxf(md,  __shfl_xor_sync(0xFFFFFFFFu, md, 2));
    mc  = fmaxf(mc,  __shfl_xor_sync(0xFFFFFFFFu, mc, 4));
    md  = fmaxf(md,  __shfl_xor_sync(0xFFFFFFFFu, md, 4));

    float is_ab, s_ab, is_c, s_c, is_d, s_d;
    make_scales(mab, &is_ab, &s_ab);
    make_scales(mc,  &is_c,  &s_c);
    make_scales(md,  &is_d,  &s_d);

    __stcs(out + 2 * i,     q4(a, is_ab, s_ab));
    __stcs(out + 2 * i + 1, q4(b, is_ab, s_ab));
    __stcs(out + i + 2 * nq, q4(c, is_c, s_c));
    __stcs(out + i + 3 * nq, q4(d, is_d, s_d));
}

extern "C" void kernel_launch(void* const* d_in, const int* in_sizes, int n_in,
                              void* d_out, int out_size) {
    const float4* x = (const float4*)d_in[0];
    float4* y = (float4*)d_out;
    int n4 = in_sizes[0] / 4;          // 8,388,608 float4
    int nq = n4 / 4;                   // 2,097,152 threads / per-slab float4
    int threads = 256;
    int blocks = (nq + threads - 1) / threads;   // 8192
    mxfp_kernel<<<blocks, threads>>>(x, y, nq);
}

// round 15
// speedup vs baseline: 1.0593x; 1.0593x over previous
#include <cuda_runtime.h>
#include <stdint.h>

// MXFP (E2M1-like, group=32) quantize-dequantize, bit-exact vs the JAX reference.
// FINAL (R2, session best: 43.49us, reconfirmed 44.1us ±0.6 noise).
//
// Structure: 4 coalesced float4 slabs per thread (MLP=4 front-batched
// LDG.128), 8 lanes per group-of-32 with a 3-stage width-8 shuffle butterfly
// max-reduction, all log2/exp2 via exponent-field bit manipulation (zero
// MUFU), streaming .cs loads and stores.
//
// Roofline verdict (14 measured experiments): 134MB read + 134MB fp32 write
// per iteration is irreducible; every correct configuration pins at
// ~6.1-6.2 TB/s steady-state mixed r/w HBM throughput. Falsified levers:
// MLP 4->8, 256-bit ld/st (L1tex wavefront splits), L2 evict_last on stores
// (poisons next replay's reads), on all input, and on half the input (all
// no-win or regression), persistent single-wave grid, ALU-pipe halving
// (pipes moved as predicted, dur unchanged -> compute non-binding), block
// 256->128. This kernel sits on the hardware floor with rel_err = 0.0.

__device__ __forceinline__ float mxfp_q1(float x, float inv_scale, float scale) {
    float xd = x * inv_scale;                       // exact (power-of-two scale)
    uint32_t bb = __float_as_uint(xd);
    uint32_t eb = bb & 0x7F800000u;                 // exponent field
    // mans*2 = |xd| * 2^(1-e);  m2 in [2,4) for normal xd
    float m2 = fabsf(xd) * __uint_as_float(0x7F800000u - eb);
    // RNE to integer via magic constant (matches rintf / jnp.round here)
    float r = (m2 + 12582912.0f) - 12582912.0f;
    // x_rnd = r * 2^(e-1)
    float ra = r * __uint_as_float(eb - 0x00800000u);
    ra = fminf(fmaxf(ra, 0.5f), 6.0f);              // clamp [min_repr, max_repr]
    if (fabsf(xd) <= 0.25f) ra = 0.0f;              // lim_zero flush (handles 0/denorm paths)
    uint32_t rb = (__float_as_uint(ra) & 0x7FFFFFFFu) | (bb & 0x80000000u);
    return __uint_as_float(rb) * scale;             // exact (power-of-two scale)
}

__device__ __forceinline__ float maxabs4(float4 v) {
    return fmaxf(fmaxf(fabsf(v.x), fabsf(v.y)), fmaxf(fabsf(v.z), fabsf(v.w)));
}

__device__ __forceinline__ float4 q4(float4 v, float inv_scale, float scale) {
    float4 o;
    o.x = mxfp_q1(v.x, inv_scale, scale);
    o.y = mxfp_q1(v.y, inv_scale, scale);
    o.z = mxfp_q1(v.z, inv_scale, scale);
    o.w = mxfp_q1(v.w, inv_scale, scale);
    return o;
}

__global__ __launch_bounds__(256) void mxfp_kernel(const float4* __restrict__ in,
                                                   float4* __restrict__ out,
                                                   int nq) {
    int i = blockIdx.x * blockDim.x + threadIdx.x;
    if (i >= nq) return;

    // ---- front-batched: 4 independent, fully-coalesced LDG.128 ----
    float4 v[4];
#pragma unroll
    for (int k = 0; k < 4; k++)
        v[k] = __ldcs(in + i + k * nq);

    // ---- local max|.| per chunk ----
    float m[4];
#pragma unroll
    for (int k = 0; k < 4; k++)
        m[k] = maxabs4(v[k]);

    // ---- 4 independent width-8 butterfly reductions, stages interleaved ----
#pragma unroll
    for (int k = 0; k < 4; k++) m[k] = fmaxf(m[k], __shfl_xor_sync(0xFFFFFFFFu, m[k], 1));
#pragma unroll
    for (int k = 0; k < 4; k++) m[k] = fmaxf(m[k], __shfl_xor_sync(0xFFFFFFFFu, m[k], 2));
#pragma unroll
    for (int k = 0; k < 4; k++) m[k] = fmaxf(m[k], __shfl_xor_sync(0xFFFFFFFFu, m[k], 4));

#pragma unroll
    for (int k = 0; k < 4; k++) {
        float mk = (m[k] == 0.0f) ? 1.0f : m[k];
        int e   = (int)(__float_as_uint(mk) >> 23) - 127;  // floor(log2) for normal mk
        int pot = e - 2;
        if (pot < -127) pot = -127;

        float inv_scale = __uint_as_float((uint32_t)(127 - pot) << 23);   // 2^-pot
        float scale = (pot >= -126)
                    ? __uint_as_float((uint32_t)(pot + 127) << 23)        // normal 2^pot
                    : __uint_as_float(0x00400000u);                       // denormal 2^-127

        __stcs(out + i + k * nq, q4(v[k], inv_scale, scale));
    }
}

extern "C" void kernel_launch(void* const* d_in, const int* in_sizes, int n_in,
                              void* d_out, int out_size) {
    const float4* x = (const float4*)d_in[0];
    float4* y = (float4*)d_out;
    int n4 = in_sizes[0] / 4;          // 8,388,608 float4
    int nq = n4 / 4;                   // 2,097,152 float4 per slab
    int threads = 256;
    int blocks = (nq + threads - 1) / threads;   // 8192
    mxfp_kernel<<<blocks, threads>>>(x, y, nq);
}